// round 2
// baseline (speedup 1.0000x reference)
#include <cuda_runtime.h>
#include <cuda_bf16.h>

// Problem constants
#define BB 16
#define TT 24
#define NN 2048
#define FF 64
#define BT (BB*TT)          // 384
#define NF (NN*FF)          // 131072
#define NF4 (NF/4)          // 32768 float4 (=ulonglong2) per (b,t) row
#define KSPLIT 8

typedef unsigned long long u64t;

// Scratch (device globals; no allocation allowed). All fully overwritten each call.
__device__ float d_rhs[BT*NN];        // 3 MB
__device__ float d_lf [BT*FF];        // lhs_f
__device__ float d_Gp [KSPLIT*BT*FF]; // K-split partials of G
__device__ float d_A  [BB*TT*TT];     // attention weights

__device__ __forceinline__ u64t pack2(float a) {
    u64t p;
    asm("mov.b64 %0, {%1, %1};" : "=l"(p) : "f"(a));
    return p;
}
__device__ __forceinline__ void ffma2(u64t& d, u64t a, u64t b) {
    asm("fma.rn.f32x2 %0, %1, %2, %0;" : "+l"(d) : "l"(a), "l"(b));
}

// ---------------------------------------------------------------------------
// Kernel 1: one pass over x per (b,t) block.
//   rhs[n]   = sum_f x[n,f]*U3[f]
//   lhs_f[f] = sum_n x[n,f]*U1[n]
// Warp layout: 8 rows per iteration; 4 lanes per row (r = lane>>2, q = lane&3).
// Lane q loads float4 #(q+4j), j=0..3 of its row (16 floats per lane per row).
// Row-dot reduce = 2 shuffles across the 4-lane group.
// ---------------------------------------------------------------------------
__global__ __launch_bounds__(256) void k1_pass(
    const float* __restrict__ x, const float* __restrict__ U1,
    const float* __restrict__ U3, float* __restrict__ rhs, float* __restrict__ lf)
{
    const int bt   = blockIdx.x;
    const int w    = threadIdx.x >> 5;
    const int lane = threadIdx.x & 31;
    const int r    = lane >> 2;
    const int q    = lane & 3;
    const float4* xb = (const float4*)(x + (size_t)bt * NF);

    float4 u3[4];
    #pragma unroll
    for (int j = 0; j < 4; j++) u3[j] = ((const float4*)U3)[q + 4*j];

    float4 acc[4];
    #pragma unroll
    for (int j = 0; j < 4; j++) acc[j] = make_float4(0.f,0.f,0.f,0.f);

    const int n0 = w * 256;
    #pragma unroll 2
    for (int k = 0; k < 32; k++) {
        const int n = n0 + 8*k + r;
        const float4* row = xb + (size_t)n * 16;
        const float u1 = __ldg(U1 + n);
        float d = 0.f;
        #pragma unroll
        for (int j = 0; j < 4; j++) {
            float4 v = row[q + 4*j];
            d += v.x*u3[j].x + v.y*u3[j].y + v.z*u3[j].z + v.w*u3[j].w;
            acc[j].x += v.x*u1; acc[j].y += v.y*u1;
            acc[j].z += v.z*u1; acc[j].w += v.w*u1;
        }
        d += __shfl_down_sync(0xffffffffu, d, 2, 4);
        d += __shfl_down_sync(0xffffffffu, d, 1, 4);
        if (q == 0) rhs[bt*NN + n] = d;
    }

    // reduce acc over r (8 row-groups) within the warp -> lanes 0..3
    #pragma unroll
    for (int off = 16; off >= 4; off >>= 1) {
        #pragma unroll
        for (int j = 0; j < 4; j++) {
            acc[j].x += __shfl_down_sync(0xffffffffu, acc[j].x, off);
            acc[j].y += __shfl_down_sync(0xffffffffu, acc[j].y, off);
            acc[j].z += __shfl_down_sync(0xffffffffu, acc[j].z, off);
            acc[j].w += __shfl_down_sync(0xffffffffu, acc[j].w, off);
        }
    }

    __shared__ float sred[8][FF];
    if (lane < 4) {
        #pragma unroll
        for (int j = 0; j < 4; j++)
            ((float4*)sred[w])[q + 4*j] = acc[j];
    }
    __syncthreads();
    if (threadIdx.x < FF) {
        float t = 0.f;
        #pragma unroll
        for (int p = 0; p < 8; p++) t += sred[p][threadIdx.x];
        lf[bt*FF + threadIdx.x] = t;
    }
}

// ---------------------------------------------------------------------------
// Kernel 2: G = rhs(384 x 2048) @ U2(2048 x 64), K-split into 8 partials.
// ---------------------------------------------------------------------------
__global__ __launch_bounds__(256) void k2_gemm(
    const float* __restrict__ rhs, const float* __restrict__ U2,
    float* __restrict__ Gp)
{
    __shared__ float Us[64*64];
    __shared__ float Rs[32*65];
    const int m0 = blockIdx.x * 32;
    const int k0 = blockIdx.y * 256;
    const int f  = threadIdx.x & 63;
    const int rg = threadIdx.x >> 6;

    float acc[8];
    #pragma unroll
    for (int r = 0; r < 8; r++) acc[r] = 0.f;

    for (int kc = 0; kc < 256; kc += 64) {
        const int kb = k0 + kc;
        __syncthreads();
        #pragma unroll
        for (int i = 0; i < 16; i++) {
            int e = threadIdx.x + i*256;
            Us[e] = U2[(size_t)(kb + (e>>6))*FF + (e & 63)];
        }
        #pragma unroll
        for (int i = 0; i < 8; i++) {
            int e = threadIdx.x + i*256;
            int row = e >> 6, kk = e & 63;
            Rs[row*65 + kk] = rhs[(size_t)(m0+row)*NN + kb + kk];
        }
        __syncthreads();
        #pragma unroll
        for (int kk = 0; kk < 64; kk++) {
            const float u = Us[kk*64 + f];
            #pragma unroll
            for (int r = 0; r < 8; r++)
                acc[r] += Rs[(rg*8 + r)*65 + kk] * u;
        }
    }
    float* g = Gp + (size_t)blockIdx.y * (BT*FF);
    #pragma unroll
    for (int r = 0; r < 8; r++)
        g[(m0 + rg*8 + r)*FF + f] = acc[r];
}

// ---------------------------------------------------------------------------
// Kernel 3: per batch b: product -> sigmoid(+be) -> E = Ve@sig -> softmax(t).
// ---------------------------------------------------------------------------
__global__ __launch_bounds__(576) void k3_scores(
    const float* __restrict__ lf, const float* __restrict__ Gp,
    const float* __restrict__ be, const float* __restrict__ Ve,
    float* __restrict__ A)
{
    const int b = blockIdx.x;
    __shared__ float lfs[TT*65], Gs[TT*65], sg[TT*25], Em[TT*25];
    __shared__ float cmax[TT], csum[TT];
    const int tid = threadIdx.x;

    for (int e = tid; e < TT*FF; e += 576) {
        int t = e >> 6, f = e & 63;
        lfs[t*65 + f] = lf[(b*TT + t)*FF + f];
        float g = 0.f;
        #pragma unroll
        for (int ks = 0; ks < KSPLIT; ks++)
            g += Gp[(size_t)ks*(BT*FF) + (b*TT + t)*FF + f];
        Gs[t*65 + f] = g;
    }
    __syncthreads();

    const int t = tid / TT;
    const int s = tid % TT;
    float p = 0.f;
    #pragma unroll
    for (int f = 0; f < FF; f++)
        p += lfs[t*65 + f] * Gs[s*65 + f];
    sg[t*25 + s] = 1.f / (1.f + __expf(-(p + be[t*TT + s])));
    __syncthreads();

    float e = 0.f;
    #pragma unroll
    for (int s2 = 0; s2 < TT; s2++)
        e += Ve[t*TT + s2] * sg[s2*25 + s];
    Em[t*25 + s] = e;
    __syncthreads();

    if (t == 0) {
        float m = -1e30f;
        #pragma unroll
        for (int tt2 = 0; tt2 < TT; tt2++) m = fmaxf(m, Em[tt2*25 + s]);
        cmax[s] = m;
    }
    __syncthreads();
    const float ex = __expf(Em[t*25 + s] - cmax[s]);
    Em[t*25 + s] = ex;
    __syncthreads();
    if (t == 0) {
        float sm = 0.f;
        #pragma unroll
        for (int tt2 = 0; tt2 < TT; tt2++) sm += Em[tt2*25 + s];
        csum[s] = sm;
    }
    __syncthreads();
    A[b*TT*TT + t*TT + s] = ex / csum[s];
}

// ---------------------------------------------------------------------------
// Kernel 4: out[b,s,nf] = sum_t x[b,t,nf] * A[b,t,s].
// x row chunk (24 x float4) held in registers as packed f32x2 pairs; A held in
// smem pre-packed (a,a) in b64 so the inner loop is LDS.64 + 2x fma.rn.f32x2.
// __launch_bounds__(256,2) caps regs at 128 -> 2 CTA/SM (16 warps) for MLP.
// ---------------------------------------------------------------------------
__global__ __launch_bounds__(256, 2) void k4_out(
    const ulonglong2* __restrict__ x16, const float* __restrict__ A,
    ulonglong2* __restrict__ out16)
{
    __shared__ u64t As2[TT*TT];
    const int b = blockIdx.y;
    for (int i = threadIdx.x; i < TT*TT; i += 256)
        As2[i] = pack2(A[b*TT*TT + i]);
    __syncthreads();

    const size_t c = (size_t)blockIdx.x * 256 + threadIdx.x;  // 16B column
    const ulonglong2* xb = x16 + (size_t)b * TT * NF4 + c;

    ulonglong2 xr[TT];
    #pragma unroll
    for (int t = 0; t < TT; t++) xr[t] = xb[(size_t)t * NF4];

    ulonglong2* ob = out16 + (size_t)b * TT * NF4 + c;
    #pragma unroll 4
    for (int s = 0; s < TT; s++) {
        u64t a0 = 0ull, a1 = 0ull;
        #pragma unroll
        for (int t = 0; t < TT; t++) {
            const u64t pa = As2[t*TT + s];
            ffma2(a0, xr[t].x, pa);
            ffma2(a1, xr[t].y, pa);
        }
        ob[(size_t)s * NF4] = make_ulonglong2(a0, a1);
    }
}

// ---------------------------------------------------------------------------
extern "C" void kernel_launch(void* const* d_in, const int* in_sizes, int n_in,
                              void* d_out, int out_size)
{
    const float* x  = (const float*)d_in[0];  // (16,24,2048,64)
    const float* U1 = (const float*)d_in[1];  // (2048)
    const float* U2 = (const float*)d_in[2];  // (2048,64)
    const float* U3 = (const float*)d_in[3];  // (64)
    const float* be = (const float*)d_in[4];  // (24,24)
    const float* Ve = (const float*)d_in[5];  // (24,24)

    float *rhs, *lf, *Gp, *A;
    cudaGetSymbolAddress((void**)&rhs, d_rhs);
    cudaGetSymbolAddress((void**)&lf,  d_lf);
    cudaGetSymbolAddress((void**)&Gp,  d_Gp);
    cudaGetSymbolAddress((void**)&A,   d_A);

    k1_pass<<<BT, 256>>>(x, U1, U3, rhs, lf);
    k2_gemm<<<dim3(BT/32, KSPLIT), 256>>>(rhs, U2, Gp);
    k3_scores<<<BB, 576>>>(lf, Gp, be, Ve, A);
    k4_out<<<dim3(NF4/256, BB), 256>>>((const ulonglong2*)x, A, (ulonglong2*)d_out);
}